// round 11
// baseline (speedup 1.0000x reference)
#include <cuda_runtime.h>
#include <cstdint>

// ---------------------------------------------------------------------------
// Problem constants
// ---------------------------------------------------------------------------
#define KK 16
#define YY 32
#define CC 16
#define NBUCKET (KK * YY)          // 512
#define ACC_ELEMS (NBUCKET * CC)   // 8192
#define KSLICE (YY * CC)           // 512 elems per k
#define NREP 32
#define EPS_F 1e-8f

#define GRIDB 1184                 // 148 SMs x 8 CTAs x 256 thr = one full wave
#define TPB 256

// Replicated scratch: 32 x 8192 f32 = 1 MB. Zero-initialized at module load;
// the in-kernel epilogue resets it, so every launch / graph replay enters
// with it zeroed. 16B-aligned for red.v4 / float4.
__device__ __align__(16) float g_acc[NREP * ACC_ELEMS];
__device__ unsigned int g_done = 0;    // CTA finish tickets
__device__ unsigned int g_done2 = 0;   // finalizer completion count

// ---------------------------------------------------------------------------
// Fused kernel. Phase 1 (all CTAs): the proven scatter loop, byte-identical.
// Phase 2 (last 16 CTAs to finish, by ticket): per-k parallel finalize —
// exactly round 9's epilogue, minus the 4-5us second-kernel launch.
//
// Residency argument: one full wave (<=32 regs via launch_bounds, 2.1KB smem)
// -> all 1184 CTAs resident -> every CTA reaches the ticket add -> the 16
// spinners always see g_done reach GRIDB. No deadlock.
// ---------------------------------------------------------------------------
__global__ void __launch_bounds__(TPB, 8)
cc_fused(const int* __restrict__ xl,
         const int* __restrict__ yl,
         const float4* __restrict__ post,
         float* __restrict__ out,
         int n_f4) {
    int tid = threadIdx.x;

    // ---- phase 1: scatter (UNCHANGED hot loop) ----
    {
        int stride = gridDim.x * blockDim.x;
        float* rep = &g_acc[(blockIdx.x & (NREP - 1)) * ACC_ELEMS];
        for (int i = blockIdx.x * blockDim.x + tid; i < n_f4; i += stride) {
            int row = i >> 2;
            int c4  = i & 3;
            float4 v = post[i];
            int b = xl[row] * YY + yl[row];          // bucket in [0,512)
            float* dst = &rep[b * CC + c4 * 4];
            asm volatile("red.global.add.v4.f32 [%0], {%1, %2, %3, %4};"
                         :: "l"(dst), "f"(v.x), "f"(v.y), "f"(v.z), "f"(v.w)
                         : "memory");
        }
    }

    // ---- ticketing ----
    __threadfence();                 // order this CTA's REDs before its ticket
    __syncthreads();
    __shared__ unsigned int s_ticket;
    if (tid == 0) s_ticket = atomicAdd(&g_done, 1u);
    __syncthreads();
    unsigned int ticket = s_ticket;
    if (ticket < GRIDB - KK) return;             // 1168 CTAs exit immediately
    int k = (int)(ticket - (GRIDB - KK));        // 0..15

    // ---- wait for all CTAs' REDs ----
    if (tid == 0) {
        while (*(volatile unsigned int*)&g_done < GRIDB) __nanosleep(64);
    }
    __syncthreads();
    __threadfence();                 // acquire side

    // ---- phase 2: finalize slice k (round-9 algorithm, 256 threads) ----
    __shared__ float s_val[KSLICE];  // 2 KB
    __shared__ float s_inv[CC];

    for (int e = tid; e < KSLICE; e += TPB) {
        int idx = k * KSLICE + e;
        float s = 0.0f;
#pragma unroll
        for (int r = 0; r < NREP; r++)
            s += g_acc[r * ACC_ELEMS + idx];
        s_val[e] = s + EPS_F;
    }
    __syncthreads();

    if (tid < CC) {
        float d = 0.0f;
#pragma unroll
        for (int y = 0; y < YY; y++)
            d += s_val[y * CC + tid];
        s_inv[tid] = 1.0f / d;
    }
    __syncthreads();

    for (int e = tid; e < KSLICE; e += TPB)
        out[k * KSLICE + e] = s_val[e] * s_inv[e & 15];

    // reset this k-slice across all replicas (disjoint across finalizers)
    {
        float4* accv = (float4*)g_acc;
        float4 z = make_float4(0.f, 0.f, 0.f, 0.f);
        int slice_f4 = KSLICE / 4;               // 128
        for (int j = tid; j < NREP * slice_f4; j += TPB) {
            int r = j / slice_f4;
            int e = j % slice_f4;
            accv[r * (ACC_ELEMS / 4) + k * slice_f4 + e] = z;
        }
    }

    // ---- counter reset: last finalizer clears both counters ----
    __threadfence();
    __syncthreads();
    if (tid == 0) {
        unsigned int t2 = atomicAdd(&g_done2, 1u);
        if (t2 == KK - 1) {                       // last finalizer; no one else
            g_done2 = 0;                          //   reads these anymore
            g_done = 0;
        }
    }
}

// ---------------------------------------------------------------------------
// Launch — single kernel.
// ---------------------------------------------------------------------------
extern "C" void kernel_launch(void* const* d_in, const int* in_sizes, int n_in,
                              void* d_out, int out_size) {
    const int*    xl   = (const int*)d_in[0];        // x_labels [N] int32
    const int*    yl   = (const int*)d_in[1];        // y_labels [N] int32
    const float4* post = (const float4*)d_in[2];     // posterior [N,16] f32
    float* out = (float*)d_out;                      // [16,32,16] f32

    int n = in_sizes[0];
    int n_f4 = n * (CC / 4);

    cc_fused<<<GRIDB, TPB>>>(xl, yl, post, out, n_f4);
}

// round 12
// speedup vs baseline: 1.3324x; 1.3324x over previous
#include <cuda_runtime.h>
#include <cstdint>

// ---------------------------------------------------------------------------
// Problem constants
// ---------------------------------------------------------------------------
#define KK 16
#define YY 32
#define CC 16
#define NBUCKET (KK * YY)          // 512
#define ACC_ELEMS (NBUCKET * CC)   // 8192
#define KSLICE (YY * CC)           // 512 elems per k
#define NREP 32
#define EPS_F 1e-8f

#define GRIDB 1184                 // 148 SMs x 8 CTAs
#define TPB 256

// Replicated scratch: 32 x 8192 f32 = 1 MB. Zero-initialized at module load;
// the in-kernel epilogue resets it, so every launch / graph replay enters
// with it zeroed. 16B-aligned for red.v4 / float4.
__device__ __align__(16) float g_acc[NREP * ACC_ELEMS];
__device__ unsigned int g_done = 0;    // CTA finish tickets
__device__ unsigned int g_done2 = 0;   // finalizer completion count

// ---------------------------------------------------------------------------
// Fused kernel. NOTE: __launch_bounds__(TPB) with NO min-blocks hint — the
// r6/r11 regressions came from the ", 8" occupancy hint capping regs at 29,
// which destroyed load pipelining (MLP) in the scatter loop (DRAM 33% vs 51%).
//
// Phase 1 (all CTAs): the proven scatter loop, byte-identical to round 9.
// Phase 2 (last 16 CTAs by finish-ticket): per-k parallel finalize.
// Deadlock-free in ANY wave schedule: non-finalizer CTAs exit right after
// ticketing, freeing SM slots for any not-yet-scheduled CTAs, so g_done
// always reaches GRIDB while the 16 spinners wait.
// ---------------------------------------------------------------------------
__global__ void __launch_bounds__(TPB)
cc_fused(const int* __restrict__ xl,
         const int* __restrict__ yl,
         const float4* __restrict__ post,
         float* __restrict__ out,
         int n_f4) {
    int tid = threadIdx.x;

    // ---- phase 1: scatter (UNCHANGED hot loop from the 77.7us build) ----
    {
        int stride = gridDim.x * blockDim.x;
        float* rep = &g_acc[(blockIdx.x & (NREP - 1)) * ACC_ELEMS];
        for (int i = blockIdx.x * blockDim.x + tid; i < n_f4; i += stride) {
            int row = i >> 2;
            int c4  = i & 3;
            float4 v = post[i];
            int b = xl[row] * YY + yl[row];          // bucket in [0,512)
            float* dst = &rep[b * CC + c4 * 4];
            asm volatile("red.global.add.v4.f32 [%0], {%1, %2, %3, %4};"
                         :: "l"(dst), "f"(v.x), "f"(v.y), "f"(v.z), "f"(v.w)
                         : "memory");
        }
    }

    // ---- ticketing ----
    __threadfence();                 // order this CTA's REDs before its ticket
    __syncthreads();
    __shared__ unsigned int s_ticket;
    if (tid == 0) s_ticket = atomicAdd(&g_done, 1u);
    __syncthreads();
    unsigned int ticket = s_ticket;
    if (ticket < GRIDB - KK) return;             // 1168 CTAs exit immediately
    int k = (int)(ticket - (GRIDB - KK));        // 0..15

    // ---- wait for all CTAs' REDs ----
    if (tid == 0) {
        while (*(volatile unsigned int*)&g_done < GRIDB) __nanosleep(64);
    }
    __syncthreads();
    __threadfence();                 // acquire side

    // ---- phase 2: finalize slice k (round-9 epilogue, 256 threads) ----
    __shared__ float s_val[KSLICE];  // 2 KB
    __shared__ float s_inv[CC];

    for (int e = tid; e < KSLICE; e += TPB) {
        int idx = k * KSLICE + e;
        float s = 0.0f;
#pragma unroll
        for (int r = 0; r < NREP; r++)
            s += g_acc[r * ACC_ELEMS + idx];
        s_val[e] = s + EPS_F;
    }
    __syncthreads();

    if (tid < CC) {
        float d = 0.0f;
#pragma unroll
        for (int y = 0; y < YY; y++)
            d += s_val[y * CC + tid];
        s_inv[tid] = 1.0f / d;
    }
    __syncthreads();

    for (int e = tid; e < KSLICE; e += TPB)
        out[k * KSLICE + e] = s_val[e] * s_inv[e & 15];

    // reset this k-slice across all replicas (disjoint across finalizers)
    {
        float4* accv = (float4*)g_acc;
        float4 z = make_float4(0.f, 0.f, 0.f, 0.f);
        int slice_f4 = KSLICE / 4;               // 128
        for (int j = tid; j < NREP * slice_f4; j += TPB) {
            int r = j / slice_f4;
            int e = j % slice_f4;
            accv[r * (ACC_ELEMS / 4) + k * slice_f4 + e] = z;
        }
    }

    // ---- counter reset: last finalizer clears both counters ----
    __threadfence();
    __syncthreads();
    if (tid == 0) {
        unsigned int t2 = atomicAdd(&g_done2, 1u);
        if (t2 == KK - 1) {                       // last finalizer; nothing
            g_done2 = 0;                          //   else reads these now
            g_done = 0;
        }
    }
}

// ---------------------------------------------------------------------------
// Launch — single kernel.
// ---------------------------------------------------------------------------
extern "C" void kernel_launch(void* const* d_in, const int* in_sizes, int n_in,
                              void* d_out, int out_size) {
    const int*    xl   = (const int*)d_in[0];        // x_labels [N] int32
    const int*    yl   = (const int*)d_in[1];        // y_labels [N] int32
    const float4* post = (const float4*)d_in[2];     // posterior [N,16] f32
    float* out = (float*)d_out;                      // [16,32,16] f32

    int n = in_sizes[0];
    int n_f4 = n * (CC / 4);

    cc_fused<<<GRIDB, TPB>>>(xl, yl, post, out, n_f4);
}

// round 13
// speedup vs baseline: 1.5318x; 1.1497x over previous
#include <cuda_runtime.h>
#include <cstdint>

// ---------------------------------------------------------------------------
// Problem constants
// ---------------------------------------------------------------------------
#define KK 16
#define YY 32
#define CC 16
#define NBUCKET (KK * YY)          // 512
#define ACC_ELEMS (NBUCKET * CC)   // 8192
#define NREP 32
#define EPS_F 1e-8f

#define SGRID 592                  // 148 SMs x 4 CTAs x 512 thr = one full wave
#define TPB 512
#define BPAD 17                    // padded bucket stride (floats) -> 17b mod 32
                                   // spreads random buckets over all smem banks

// Replicated scratch: 32 x 8192 f32 = 1 MB. Zero-initialized at module load;
// cc_finalize resets it after reading, so every launch / graph replay enters
// with it zeroed. 16B-aligned for red.v4.
__device__ __align__(16) float g_acc[NREP * ACC_ELEMS];

__device__ __forceinline__ void red_v4(float* dst, float x, float y, float z, float w) {
    asm volatile("red.global.add.v4.f32 [%0], {%1, %2, %3, %4};"
                 :: "l"(dst), "f"(x), "f"(y), "f"(z), "f"(w)
                 : "memory");
}

// ---------------------------------------------------------------------------
// Kernel 1: hybrid scatter-add. The L2 atomic ALU (REDG) is the measured
// bottleneck (~1.29 cyc/lane); the smem atomic ALU is idle. Route 1/8 of the
// traffic (warp-uniform rotation, no divergence) into a per-CTA bank-padded
// smem accumulator; the rest goes direct via red.global.add.v4. Flush smem
// at the end. Both sinks feed the same replicated g_acc.
// ---------------------------------------------------------------------------
__global__ void __launch_bounds__(TPB)
cc_scatter(const int* __restrict__ xl,
           const int* __restrict__ yl,
           const float4* __restrict__ post,
           int n_f4) {
    __shared__ float s_acc[NBUCKET * BPAD];    // 34,816 B
    int tid = threadIdx.x;
    int wid = tid >> 5;                        // warp 0..15

    // zero smem accumulator
    for (int e = tid; e < NBUCKET * BPAD; e += TPB) s_acc[e] = 0.0f;
    __syncthreads();

    float* rep = &g_acc[(blockIdx.x & (NREP - 1)) * ACC_ELEMS];
    int stride = gridDim.x * blockDim.x;
    int it = 0;
    for (int i = blockIdx.x * blockDim.x + tid; i < n_f4; i += stride, ++it) {
        int row = i >> 2;
        int c4  = i & 3;
        float4 v = post[i];
        int b = xl[row] * YY + yl[row];        // bucket in [0,512)
        if (((it ^ wid) & 7) == 0) {
            // smem sink (1/8 of iterations per warp, warp-uniform)
            float* s = &s_acc[b * BPAD + c4 * 4];
            atomicAdd(s + 0, v.x);
            atomicAdd(s + 1, v.y);
            atomicAdd(s + 2, v.z);
            atomicAdd(s + 3, v.w);
        } else {
            // L2 sink (7/8)
            red_v4(&rep[b * CC + c4 * 4], v.x, v.y, v.z, v.w);
        }
    }
    __syncthreads();

    // flush smem accumulator: thread t owns bucket t (512 = TPB).
    // LDS pattern (17t + j) mod 32 is a bank permutation across lanes.
    {
        int b = tid;
        const float* s = &s_acc[b * BPAD];
        float* dst = &rep[b * CC];
#pragma unroll
        for (int j = 0; j < 4; j++)
            red_v4(dst + j * 4, s[j * 4 + 0], s[j * 4 + 1], s[j * 4 + 2], s[j * 4 + 3]);
    }
}

// ---------------------------------------------------------------------------
// Kernel 2: finalize (round-9 verbatim). 16 blocks (one per k), 512 threads
// (one per (y,c)): replica-sum (MLP=32), Y-normalize, write, reset scratch.
// ---------------------------------------------------------------------------
__global__ void __launch_bounds__(512)
cc_finalize(float* __restrict__ out) {
    __shared__ float s_val[YY * CC];
    __shared__ float s_inv[CC];

    int k   = blockIdx.x;                // 0..15
    int tid = threadIdx.x;               // 0..511
    int elem = k * (YY * CC) + tid;

    float s = 0.0f;
#pragma unroll
    for (int r = 0; r < NREP; r++)
        s += g_acc[r * ACC_ELEMS + elem];
    float v = s + EPS_F;
    s_val[tid] = v;
    __syncthreads();

    if (tid < CC) {
        float d = 0.0f;
#pragma unroll
        for (int y = 0; y < YY; y++)
            d += s_val[y * CC + tid];
        s_inv[tid] = 1.0f / d;
    }
    __syncthreads();

    out[elem] = v * s_inv[tid & 15];

    // reset this element's replica slots for the next launch / graph replay
#pragma unroll
    for (int r = 0; r < NREP; r++)
        g_acc[r * ACC_ELEMS + elem] = 0.0f;
}

// ---------------------------------------------------------------------------
// Launch
// ---------------------------------------------------------------------------
extern "C" void kernel_launch(void* const* d_in, const int* in_sizes, int n_in,
                              void* d_out, int out_size) {
    const int*    xl   = (const int*)d_in[0];        // x_labels [N] int32
    const int*    yl   = (const int*)d_in[1];        // y_labels [N] int32
    const float4* post = (const float4*)d_in[2];     // posterior [N,16] f32
    float* out = (float*)d_out;                      // [16,32,16] f32

    int n = in_sizes[0];
    int n_f4 = n * (CC / 4);

    static bool attr_set = false;
    if (!attr_set) {
        // ask for max smem carveout so 4 CTAs x 34.8KB fit per SM
        cudaFuncSetAttribute(cc_scatter,
                             cudaFuncAttributePreferredSharedMemoryCarveout,
                             cudaSharedmemCarveoutMaxShared);
        attr_set = true;
    }

    cc_scatter<<<SGRID, TPB>>>(xl, yl, post, n_f4);
    cc_finalize<<<KK, 512>>>(out);
}